// round 16
// baseline (speedup 1.0000x reference)
#include <cuda_runtime.h>
#include <cuda_fp16.h>
#include <math.h>
#include <stdint.h>

// Problem constants (fixed shapes)
#define BB 2
#define LL 4096
#define DM 512
#define NH 8
#define HD 64
#define SK 45                 // sample_k = n_top = min(5*ceil(ln(4096)), 4096)
#define BH (BB*NH)
#define NSEG 32
#define SEGL (LL/NSEG)        // 128
#define JSEGS 32              // j-splits for upd partial sums (128 keys each)
#define MM (BB*LL)            // 8192 rows

// Scratch (device globals — no allocation allowed in kernel_launch)
__device__ float g_Q[BB*NH*LL*HD];
__device__ float g_K[BB*NH*LL*HD];
__device__ float g_V[BB*NH*LL*HD];
__device__ float g_m[BH*LL];
__device__ int   g_top[BH*SK];
__device__ float g_seg[BH*NSEG*HD];
__device__ float g_part[BH*JSEGS*SK*HD];
__device__ float g_rowsum[BH*SK];
// fp16 split scratch (hi/lo pair; 16B-aligned for cp.async)
__device__ __align__(16) uint16_t g_Ah[3u*MM*DM];
__device__ __align__(16) uint16_t g_Al[3u*MM*DM];
__device__ __align__(16) uint16_t g_Wh[3u*DM*DM];   // transposed: [n][k]
__device__ __align__(16) uint16_t g_Wl[3u*DM*DM];

// ===========================================================================
// helpers (legacy mma.sync path — compiles at compute_103 baseline)
// ===========================================================================
__device__ __forceinline__ void mma_f16(float c[4], uint32_t a0, uint32_t a1,
                                        uint32_t a2, uint32_t a3,
                                        uint32_t b0, uint32_t b1) {
    asm volatile(
        "mma.sync.aligned.m16n8k16.row.col.f32.f16.f16.f32 "
        "{%0,%1,%2,%3}, {%4,%5,%6,%7}, {%8,%9}, {%0,%1,%2,%3};"
        : "+f"(c[0]), "+f"(c[1]), "+f"(c[2]), "+f"(c[3])
        : "r"(a0), "r"(a1), "r"(a2), "r"(a3), "r"(b0), "r"(b1));
}
__device__ __forceinline__ uint32_t smem_addr_u32(const void* p) {
    uint32_t a;
    asm("{ .reg .u64 t; cvta.to.shared.u64 t, %1; cvt.u32.u64 %0, t; }" : "=r"(a) : "l"(p));
    return a;
}
#define CP_ASYNC16(dst, src) \
    asm volatile("cp.async.cg.shared.global [%0], [%1], 16;" :: "r"(dst), "l"(src))
#define CP_COMMIT() asm volatile("cp.async.commit_group;" ::: "memory")
#define CP_WAIT(n)  asm volatile("cp.async.wait_group %0;" :: "n"(n) : "memory")
#define LDSM_X4(r0, r1, r2, r3, addr) \
    asm volatile("ldmatrix.sync.aligned.m8n8.x4.shared.b16 {%0,%1,%2,%3}, [%4];" \
                 : "=r"(r0), "=r"(r1), "=r"(r2), "=r"(r3) : "r"(addr))

__device__ __forceinline__ void split_h(float x, uint16_t& h, uint16_t& l) {
    __half a0 = __float2half_rn(x);
    float r = x - __half2float(a0);
    __half a1 = __float2half_rn(r);
    h = __half_as_ushort(a0);
    l = __half_as_ushort(a1);
}

// ---------------------------------------------------------------------------
// K0 (merged): blockIdx.x < 2048 -> X split (8 floats/thread);
// else -> W transpose+split (32x32 tiles). z = blockIdx.y selects q/k/v.
// ---------------------------------------------------------------------------
__global__ __launch_bounds__(256) void k_split(
    const float* __restrict__ X0, const float* __restrict__ X1, const float* __restrict__ X2,
    const float* __restrict__ W0, const float* __restrict__ W1, const float* __restrict__ W2)
{
    __shared__ float t[32][33];
    int z = blockIdx.y;
    int tid = threadIdx.x;
    if (blockIdx.x < 2048) {
        const float* X = (z == 0) ? X0 : (z == 1) ? X1 : X2;
        size_t i = (size_t)blockIdx.x * 256 + tid;          // group-of-8 index
        float4 v0 = ((const float4*)X)[2 * i];
        float4 v1 = ((const float4*)X)[2 * i + 1];
        float xs[8] = {v0.x, v0.y, v0.z, v0.w, v1.x, v1.y, v1.z, v1.w};
        uint16_t h[8], l[8];
        #pragma unroll
        for (int j = 0; j < 8; j++) split_h(xs[j], h[j], l[j]);
        uint4 hp, lp;
        hp.x = h[0] | ((uint32_t)h[1] << 16); hp.y = h[2] | ((uint32_t)h[3] << 16);
        hp.z = h[4] | ((uint32_t)h[5] << 16); hp.w = h[6] | ((uint32_t)h[7] << 16);
        lp.x = l[0] | ((uint32_t)l[1] << 16); lp.y = l[2] | ((uint32_t)l[3] << 16);
        lp.z = l[4] | ((uint32_t)l[5] << 16); lp.w = l[6] | ((uint32_t)l[7] << 16);
        size_t base = (size_t)z * MM * DM / 8;
        ((uint4*)g_Ah)[base + i] = hp;
        ((uint4*)g_Al)[base + i] = lp;
    } else {
        const float* W = (z == 0) ? W0 : (z == 1) ? W1 : W2;
        int id = blockIdx.x - 2048;          // 0..255
        int bx = (id & 15) * 32;             // n tile
        int by = (id >> 4) * 32;             // k tile
        int tx = tid & 31, ty = tid >> 5;    // (32, 8)
        #pragma unroll
        for (int r = ty; r < 32; r += 8)
            t[r][tx] = W[(size_t)(by + r) * DM + bx + tx];
        __syncthreads();
        size_t zoff = (size_t)z * DM * DM;
        #pragma unroll
        for (int r = ty; r < 32; r += 8) {
            float x = t[tx][r];              // = W[by+tx][bx+r]
            uint16_t h, l;
            split_h(x, h, l);
            g_Wh[zoff + (size_t)(bx + r) * DM + by + tx] = h;
            g_Wl[zoff + (size_t)(bx + r) * DM + by + tx] = l;
        }
    }
}

// ---------------------------------------------------------------------------
// K1: projection GEMM, 3xFP16 mma.sync (a0b0 + a1b0 + a0b1), cp.async double
// buffer + ldmatrix. CTA tile 128x128, BK=32, 8 warps 2(m)x4(n), warp 64x32.
// ---------------------------------------------------------------------------
#define RSTH 40                        // row stride in halfs
#define TILE_H (128 * RSTH)            // 5120 halfs per tile
#define STAGE_H (4 * TILE_H)           // 20480 halfs per stage
#define PROJ_SMEM_BYTES (2 * STAGE_H * 2)   // 81920 B

__device__ __forceinline__ void ld_stage(uint32_t smb,
    const uint16_t* __restrict__ Ah, const uint16_t* __restrict__ Al,
    const uint16_t* __restrict__ Bh, const uint16_t* __restrict__ Bl,
    int k0, int tid)
{
    #pragma unroll
    for (int t = 0; t < 2; t++) {
        int idx = tid + t * 256;             // 0..511
        int row = idx >> 2;                  // 0..127
        int ch  = (idx & 3) * 8;             // half offset 0,8,16,24
        uint32_t d = smb + (uint32_t)(row * RSTH + ch) * 2;
        size_t s = (size_t)row * DM + k0 + ch;
        CP_ASYNC16(d,                    Ah + s);
        CP_ASYNC16(d + TILE_H * 2,       Al + s);
        CP_ASYNC16(d + 2 * TILE_H * 2,   Bh + s);
        CP_ASYNC16(d + 3 * TILE_H * 2,   Bl + s);
    }
}

__global__ __launch_bounds__(256, 2) void k_proj_mma2(
    const float* __restrict__ bq, const float* __restrict__ bk, const float* __restrict__ bv)
{
    extern __shared__ uint16_t smem_h[];
    const int z = blockIdx.z;
    const float* bias = (z == 0) ? bq : (z == 1) ? bk : bv;
    float* dst = (z == 0) ? g_Q : (z == 1) ? g_K : g_V;

    const int tid  = threadIdx.x;
    const int wid  = tid >> 5;
    const int lane = tid & 31;
    const int warp_m = wid >> 2;             // 0..1
    const int warp_n = wid & 3;              // 0..3
    const int m0 = blockIdx.y * 128;
    const int n0 = blockIdx.x * 128;

    const uint16_t* Ah = g_Ah + (size_t)z * MM * DM + (size_t)m0 * DM;
    const uint16_t* Al = g_Al + (size_t)z * MM * DM + (size_t)m0 * DM;
    const uint16_t* Bh = g_Wh + (size_t)z * DM * DM + (size_t)n0 * DM;
    const uint16_t* Bl = g_Wl + (size_t)z * DM * DM + (size_t)n0 * DM;

    const uint32_t smb = smem_addr_u32(smem_h);

    float c[4][4][4];
    #pragma unroll
    for (int mt = 0; mt < 4; mt++)
        #pragma unroll
        for (int nt = 0; nt < 4; nt++)
            #pragma unroll
            for (int i = 0; i < 4; i++) c[mt][nt][i] = 0.f;

    const int l7 = lane & 7;
    const int aRow  = warp_m * 64 + l7 + ((lane >> 3) & 1) * 8;
    const int aColH = ((lane >> 4) & 1) * 8;
    const int bRow  = warp_n * 32 + l7 + ((lane >> 4) & 1) * 8;
    const int bColH = ((lane >> 3) & 1) * 8;

    ld_stage(smb, Ah, Al, Bh, Bl, 0, tid);
    CP_COMMIT();

    const int NCHUNK = DM / 32;              // 16
    for (int ck = 0; ck < NCHUNK; ck++) {
        if (ck + 1 < NCHUNK) {
            ld_stage(smb + ((ck + 1) & 1) * STAGE_H * 2, Ah, Al, Bh, Bl, (ck + 1) * 32, tid);
            CP_COMMIT();
            CP_WAIT(1);
        } else {
            CP_WAIT(0);
        }
        __syncthreads();

        const uint32_t stage = smb + (ck & 1) * STAGE_H * 2;
        #pragma unroll
        for (int prod = 0; prod < 3; prod++) {
            const uint32_t aoff = stage + (prod == 1 ? TILE_H * 2 : 0);
            const uint32_t boff = stage + 2 * TILE_H * 2 + (prod == 2 ? TILE_H * 2 : 0);
            #pragma unroll
            for (int ks = 0; ks < 2; ks++) {
                const int kb = ks * 16;
                uint32_t af[4][4];
                #pragma unroll
                for (int mt = 0; mt < 4; mt++) {
                    uint32_t addr = aoff + (uint32_t)(((aRow + mt * 16) * RSTH) + kb + aColH) * 2;
                    LDSM_X4(af[mt][0], af[mt][1], af[mt][2], af[mt][3], addr);
                }
                uint32_t bf[4][2];
                #pragma unroll
                for (int pr = 0; pr < 2; pr++) {
                    uint32_t addr = boff + (uint32_t)(((bRow + pr * 16) * RSTH) + kb + bColH) * 2;
                    LDSM_X4(bf[pr * 2][0], bf[pr * 2][1], bf[pr * 2 + 1][0], bf[pr * 2 + 1][1], addr);
                }
                #pragma unroll
                for (int mt = 0; mt < 4; mt++)
                    #pragma unroll
                    for (int nt = 0; nt < 4; nt++)
                        mma_f16(c[mt][nt], af[mt][0], af[mt][1], af[mt][2], af[mt][3],
                                bf[nt][0], bf[nt][1]);
            }
        }
        __syncthreads();
    }

    // ---- epilogue: accum -> smem staging (stride 132 floats) -> coalesced ----
    float* stg = (float*)smem_h;             // 128 x 132 floats = 67584 B
    const int fr = lane >> 2, fk = lane & 3;
    #pragma unroll
    for (int mt = 0; mt < 4; mt++) {
        #pragma unroll
        for (int nt = 0; nt < 4; nt++) {
            int m = warp_m * 64 + mt * 16 + fr;
            int n = warp_n * 32 + nt * 8 + fk * 2;
            stg[m * 132 + n]           = c[mt][nt][0];
            stg[m * 132 + n + 1]       = c[mt][nt][1];
            stg[(m + 8) * 132 + n]     = c[mt][nt][2];
            stg[(m + 8) * 132 + n + 1] = c[mt][nt][3];
        }
    }
    __syncthreads();
    for (int i = tid; i < 128 * 128; i += 256) {
        int row = i >> 7, col = i & 127;
        int n = n0 + col;
        int h = n >> 6, dd = n & 63;
        int mi = m0 + row;
        int b_ = mi >> 12, l = mi & (LL - 1);
        dst[(((size_t)(b_ * NH + h) * LL) + l) * HD + dd] = stg[row * 132 + col] + bias[n];
    }
}

// ---------------------------------------------------------------------------
// K1b: segment totals prepass: g_seg[bh][seg][d] = sum_{r in seg} V[bh][r][d].
// ---------------------------------------------------------------------------
__global__ __launch_bounds__(256) void k_segtot() {
    __shared__ float part[4 * HD];
    int seg = blockIdx.x, bh = blockIdx.y, tid = threadIdx.x;
    int d = tid & 63, q = tid >> 6;
    const float* Vb = g_V + (size_t)bh * LL * HD + (size_t)seg * SEGL * HD;
    float s = 0.f;
    #pragma unroll 8
    for (int r = 0; r < 32; r++) s += Vb[(q * 32 + r) * HD + d];
    part[q * HD + d] = s;
    __syncthreads();
    if (tid < HD)
        g_seg[((size_t)bh * NSEG + seg) * HD + tid] =
            part[tid] + part[HD + tid] + part[2 * HD + tid] + part[3 * HD + tid];
}

// ---------------------------------------------------------------------------
// K2 (fused): blockIdx.x < 128 -> mscore; else -> cumsum segment (stage-free
// 2-pass register scan, global prefix from g_seg). Small static smem (~8 KB)
// so occupancy is warp-limited (8 blocks/SM) — gathers get full latency hiding.
// ---------------------------------------------------------------------------
__global__ __launch_bounds__(256) void k_fused1(const int* __restrict__ idx,
                                                float* __restrict__ out) {
    __shared__ int   sidx[32 * SK];          // 5.76 KB (mscore)
    __shared__ float qtot[4 * HD];           // 1 KB   (cumsum)
    __shared__ float gpart[4 * HD];          // 1 KB
    __shared__ float goffs[HD];              // 256 B
    int tid = threadIdx.x;
    int bh = blockIdx.y;
    if (blockIdx.x < LL / 32) {
        // ---------------- mscore ----------------
        int l0 = blockIdx.x * 32;
        for (int i = tid; i < 32 * SK; i += 256) sidx[i] = idx[l0 * SK + i];
        __syncthreads();
        int wid = tid >> 5, lane = tid & 31;
        int grp = lane >> 3, sub = lane & 7;
        int lrel = wid * 4 + grp;
        int l = l0 + lrel;
        const float* Qb = g_Q + (size_t)bh * LL * HD;
        const float* Kb = g_K + (size_t)bh * LL * HD;
        float4 q0 = *(const float4*)&Qb[(size_t)l * HD + sub * 8];
        float4 q1 = *(const float4*)&Qb[(size_t)l * HD + sub * 8 + 4];
        const int* myidx = &sidx[lrel * SK];
        float mx = -INFINITY, sm = 0.f;
        #pragma unroll 6
        for (int s = 0; s < SK; s++) {
            int j = myidx[s];
            const float* kr = &Kb[(size_t)j * HD + sub * 8];
            float4 k0 = *(const float4*)kr;
            float4 k1 = *(const float4*)(kr + 4);
            float p = q0.x*k0.x + q0.y*k0.y + q0.z*k0.z + q0.w*k0.w
                    + q1.x*k1.x + q1.y*k1.y + q1.z*k1.z + q1.w*k1.w;
            p += __shfl_xor_sync(0xffffffffu, p, 4);
            p += __shfl_xor_sync(0xffffffffu, p, 2);
            p += __shfl_xor_sync(0xffffffffu, p, 1);
            mx = fmaxf(mx, p);
            sm += p;
        }
        if (sub == 0) g_m[bh * LL + l] = mx - sm * (1.f / LL);
    } else {
        // -------- cumsum segment: stage-free 2-pass scan + global prefix ----
        int seg = blockIdx.x - LL / 32;       // 0..31
        const float* Vb = g_V + (size_t)bh * LL * HD + (size_t)seg * SEGL * HD;
        int d = tid & 63, q = tid >> 6;
        // global prefix partials (4 groups x 8 segments)
        {
            float s = 0.f;
            int lo = q * 8, hi = min(seg, lo + 8);
            for (int ss = lo; ss < hi; ss++)
                s += g_seg[((size_t)bh * NSEG + ss) * HD + d];
            gpart[q * HD + d] = s;
        }
        // pass 1: quarter totals
        float acc = 0.f;
        #pragma unroll 8
        for (int r = 0; r < 32; r++) acc += Vb[(q * 32 + r) * HD + d];
        qtot[q * HD + d] = acc;
        __syncthreads();
        if (tid < HD)
            goffs[tid] = gpart[tid] + gpart[HD + tid] + gpart[2 * HD + tid] + gpart[3 * HD + tid];
        __syncthreads();
        float pre = goffs[d];
        for (int qq = 0; qq < q; qq++) pre += qtot[qq * HD + d];
        // pass 2: re-read, scan, write final
        int b_ = bh >> 3, h = bh & 7;
        float* ob = out + ((size_t)b_ * LL + seg * SEGL) * DM + h * HD + d;
        acc = pre;
        #pragma unroll 8
        for (int r = 0; r < 32; r++) {
            acc += Vb[(q * 32 + r) * HD + d];
            ob[(size_t)(q * 32 + r) * DM] = acc;
        }
    }
}

// ---------------------------------------------------------------------------
// K3: radix top-45 per (b,h) (also zeroes g_rowsum). Grid = BH.
// ---------------------------------------------------------------------------
__global__ __launch_bounds__(256) void k_topk() {
    __shared__ uint32_t keys[LL];            // 16 KB
    __shared__ uint32_t hist[256];
    __shared__ uint32_t s_prefix, s_need;
    __shared__ int s_cnt, s_eq;
    __shared__ int eq_list[256];
    int bh = blockIdx.x, tid = threadIdx.x;
    if (tid < SK) g_rowsum[bh * SK + tid] = 0.f;
    for (int i = tid; i < LL; i += 256) {
        uint32_t u = __float_as_uint(g_m[bh * LL + i]);
        keys[i] = (u & 0x80000000u) ? ~u : (u | 0x80000000u);
    }
    if (tid == 0) { s_prefix = 0; s_need = SK; s_cnt = 0; s_eq = 0; }
    __syncthreads();
    for (int level = 0; level < 4; level++) {
        int shift = 24 - 8 * level;
        uint32_t pmask = (level == 0) ? 0u : (0xFFFFFFFFu << (shift + 8));
        hist[tid] = 0;
        __syncthreads();
        uint32_t prefix = s_prefix;
        for (int i = tid; i < LL; i += 256) {
            uint32_t u = keys[i];
            if ((u & pmask) == prefix) atomicAdd(&hist[(u >> shift) & 0xFFu], 1u);
        }
        __syncthreads();
        if (tid == 0) {
            uint32_t need = s_need, S = 0; int b;
            for (b = 255; b > 0; b--) {
                if (S + hist[b] >= need) break;
                S += hist[b];
            }
            s_prefix = prefix | ((uint32_t)b << shift);
            s_need = need - S;
        }
        __syncthreads();
    }
    uint32_t thresh = s_prefix;
    uint32_t need_eq = s_need;
    for (int i = tid; i < LL; i += 256) {
        uint32_t u = keys[i];
        if (u > thresh) {
            int p = atomicAdd(&s_cnt, 1);
            g_top[bh * SK + p] = i;
        } else if (u == thresh) {
            int p = atomicAdd(&s_eq, 1);
            if (p < 256) eq_list[p] = i;
        }
    }
    __syncthreads();
    if (tid == 0) {
        int E = s_eq < 256 ? s_eq : 256;
        int base = s_cnt;
        for (uint32_t t = 0; t < need_eq; t++) {
            int best = 1 << 30, bj = 0;
            for (int j2 = 0; j2 < E; j2++)
                if (eq_list[j2] < best) { best = eq_list[j2]; bj = j2; }
            g_top[bh * SK + base + t] = best;
            eq_list[bj] = 1 << 30;
        }
    }
}

// ---------------------------------------------------------------------------
// K4: fused scores+updpart. Block = (jseg of 128 keys, bh); JSEGS=32 for
// load balance under the causal skip. V staged TRANSPOSED (vs[d][jj],
// stride 68) so the accumulate is float4 x float4 (conflict-free LDS.128).
// ---------------------------------------------------------------------------
#define SU_QS 0
#define SU_KS (SK*HD)                 // 2880
#define SU_VS (SU_KS + 64*68)         // 7232
#define SU_ES (SU_VS + 64*68)         // 11584
#define SU_FLOATS (SU_ES + SK*64)     // 14464
#define SU_BYTES (SU_FLOATS * 4)      // 57856

__global__ __launch_bounds__(256) void k_scoreupd() {
    extern __shared__ float sm[];
    __shared__ int   tp[SK];
    __shared__ float rs[SK];
    int jseg = blockIdx.x, bh = blockIdx.y, tid = threadIdx.x;
    const float* Qb = g_Q + (size_t)bh * LL * HD;
    const float* Kb = g_K + (size_t)bh * LL * HD;
    const float* Vb = g_V + (size_t)bh * LL * HD;
    if (tid < SK) { tp[tid] = g_top[bh * SK + tid]; rs[tid] = 0.f; }
    __syncthreads();
    float* qs = sm + SU_QS;
    float* ks = sm + SU_KS;
    float* vs = sm + SU_VS;   // transposed: vs[d*68 + jj]
    float* es = sm + SU_ES;
    for (int i = tid; i < SK * HD; i += 256)
        qs[i] = Qb[(size_t)tp[i >> 6] * HD + (i & 63)];
    int key = tid & 63, ug = tid >> 6;
    float acc[12];
    #pragma unroll
    for (int c = 0; c < 12; c++) acc[c] = 0.f;

    for (int sc = 0; sc < 2; sc++) {
        int jc = jseg * 128 + sc * 64;
        __syncthreads();                      // protect ks/vs/es reuse
        for (int i = tid; i < 64 * HD; i += 256) {
            int jj = i >> 6, dd = i & 63;
            ks[jj * 68 + dd] = Kb[(size_t)(jc + jj) * HD + dd];
            vs[dd * 68 + jj] = Vb[(size_t)(jc + jj) * HD + dd];
        }
        __syncthreads();
        const float4* ka = (const float4*)&ks[key * 68];
        for (int u = ug; u < SK; u += 4) {
            int t = tp[u];
            if (t >= jc) {                    // warp-uniform
                const float4* qa = (const float4*)&qs[u * HD];
                float a = 0.f;
                #pragma unroll
                for (int dq = 0; dq < 16; dq++) {
                    float4 qq = qa[dq], kk = ka[dq];
                    a += qq.x * kk.x + qq.y * kk.y + qq.z * kk.z + qq.w * kk.w;
                }
                float e = (jc + key > t) ? 0.f : __expf(a * 0.125f);
                es[u * 64 + key] = e;
                float r = e;
                #pragma unroll
                for (int o = 16; o; o >>= 1) r += __shfl_xor_sync(0xffffffffu, r, o);
                if ((tid & 31) == 0) atomicAdd(&rs[u], r);
            } else {
                es[u * 64 + key] = 0.f;
            }
        }
        __syncthreads();
        // accumulate e . V with transposed vs: float4 x float4
        const float4* va = (const float4*)&vs[key * 68];
        int c = 0;
        for (int u = ug; u < SK; u += 4, c++) {
            if (tp[u] >= jc) {                // warp-uniform
                const float4* ea = (const float4*)&es[u * 64];
                float a = acc[c];
                #pragma unroll
                for (int j4 = 0; j4 < 16; j4++) {
                    float4 ee = ea[j4], vv = va[j4];
                    a += ee.x * vv.x + ee.y * vv.y + ee.z * vv.z + ee.w * vv.w;
                }
                acc[c] = a;
            }
        }
    }
    __syncthreads();
    int c = 0;
    for (int u = ug; u < SK; u += 4, c++)
        g_part[(((size_t)bh * JSEGS + jseg) * SK + u) * HD + key] = acc[c];
    if (tid < SK && rs[tid] != 0.f) atomicAdd(&g_rowsum[bh * SK + tid], rs[tid]);
}

// K5: reduce partials, normalize by row sum, scatter into out at top rows.
__global__ void k_scatter(float* __restrict__ out) {
    int u = blockIdx.x, bh = blockIdx.y, d = threadIdx.x;
    float s = 0.f;
    #pragma unroll
    for (int seg = 0; seg < JSEGS; seg++)
        s += g_part[(((size_t)bh * JSEGS + seg) * SK + u) * HD + d];
    s *= (1.f / g_rowsum[bh * SK + u]);
    int b_ = bh >> 3, h = bh & 7, l = g_top[bh * SK + u];
    out[((size_t)b_ * LL + l) * DM + h * HD + d] = s;
}

// ---------------------------------------------------------------------------
extern "C" void kernel_launch(void* const* d_in, const int* in_sizes, int n_in,
                              void* d_out, int out_size) {
    const float* queries = (const float*)d_in[0];
    const float* keys    = (const float*)d_in[1];
    const float* values  = (const float*)d_in[2];
    const float* Wq = (const float*)d_in[3];
    const float* bq = (const float*)d_in[4];
    const float* Wk = (const float*)d_in[5];
    const float* bk = (const float*)d_in[6];
    const float* Wv = (const float*)d_in[7];
    const float* bv = (const float*)d_in[8];
    const int*   idx = (const int*)d_in[9];
    float* out = (float*)d_out;

    cudaFuncSetAttribute(k_proj_mma2, cudaFuncAttributeMaxDynamicSharedMemorySize,
                         PROJ_SMEM_BYTES);
    cudaFuncSetAttribute(k_scoreupd, cudaFuncAttributeMaxDynamicSharedMemorySize,
                         SU_BYTES);

    k_split<<<dim3(2048 + 256, 3), 256>>>(queries, keys, values, Wq, Wk, Wv);
    k_proj_mma2<<<dim3(DM / 128, MM / 128, 3), 256, PROJ_SMEM_BYTES>>>(bq, bk, bv);
    k_segtot<<<dim3(NSEG, BH), 256>>>();
    k_fused1<<<dim3(LL / 32 + NSEG, BH), 256>>>(idx, out);
    k_topk<<<BH, 256>>>();
    k_scoreupd<<<dim3(JSEGS, BH), 256, SU_BYTES>>>();
    k_scatter<<<dim3(SK, BH), 64>>>(out);
}

// round 17
// speedup vs baseline: 1.0469x; 1.0469x over previous
#include <cuda_runtime.h>
#include <cuda_fp16.h>
#include <math.h>
#include <stdint.h>

// Problem constants (fixed shapes)
#define BB 2
#define LL 4096
#define DM 512
#define NH 8
#define HD 64
#define SK 45                 // sample_k = n_top = min(5*ceil(ln(4096)), 4096)
#define BH (BB*NH)
#define NSEG 32
#define SEGL (LL/NSEG)        // 128
#define JSEGS 32              // j-splits for upd partial sums (128 keys each)
#define MM (BB*LL)            // 8192 rows

// Scratch (device globals — no allocation allowed in kernel_launch)
__device__ float g_Q[BB*NH*LL*HD];
__device__ float g_K[BB*NH*LL*HD];
__device__ float g_V[BB*NH*LL*HD];
__device__ float g_m[BH*LL];
__device__ int   g_top[BH*SK];
__device__ float g_seg[BH*NSEG*HD];
__device__ float g_part[BH*JSEGS*SK*HD];
__device__ float g_rowsum[BH*SK];
// fp16 split scratch (hi/lo pair; 16B-aligned for cp.async)
__device__ __align__(16) uint16_t g_Ah[3u*MM*DM];
__device__ __align__(16) uint16_t g_Al[3u*MM*DM];
__device__ __align__(16) uint16_t g_Wh[3u*DM*DM];   // transposed: [n][k]
__device__ __align__(16) uint16_t g_Wl[3u*DM*DM];

// ===========================================================================
// helpers (legacy mma.sync path — compiles at compute_103 baseline)
// ===========================================================================
__device__ __forceinline__ void mma_f16(float c[4], uint32_t a0, uint32_t a1,
                                        uint32_t a2, uint32_t a3,
                                        uint32_t b0, uint32_t b1) {
    asm volatile(
        "mma.sync.aligned.m16n8k16.row.col.f32.f16.f16.f32 "
        "{%0,%1,%2,%3}, {%4,%5,%6,%7}, {%8,%9}, {%0,%1,%2,%3};"
        : "+f"(c[0]), "+f"(c[1]), "+f"(c[2]), "+f"(c[3])
        : "r"(a0), "r"(a1), "r"(a2), "r"(a3), "r"(b0), "r"(b1));
}
__device__ __forceinline__ uint32_t smem_addr_u32(const void* p) {
    uint32_t a;
    asm("{ .reg .u64 t; cvta.to.shared.u64 t, %1; cvt.u32.u64 %0, t; }" : "=r"(a) : "l"(p));
    return a;
}
#define CP_ASYNC16(dst, src) \
    asm volatile("cp.async.cg.shared.global [%0], [%1], 16;" :: "r"(dst), "l"(src))
#define CP_COMMIT() asm volatile("cp.async.commit_group;" ::: "memory")
#define CP_WAIT(n)  asm volatile("cp.async.wait_group %0;" :: "n"(n) : "memory")
#define LDSM_X4(r0, r1, r2, r3, addr) \
    asm volatile("ldmatrix.sync.aligned.m8n8.x4.shared.b16 {%0,%1,%2,%3}, [%4];" \
                 : "=r"(r0), "=r"(r1), "=r"(r2), "=r"(r3) : "r"(addr))

__device__ __forceinline__ void split_h(float x, uint16_t& h, uint16_t& l) {
    __half a0 = __float2half_rn(x);
    float r = x - __half2float(a0);
    __half a1 = __float2half_rn(r);
    h = __half_as_ushort(a0);
    l = __half_as_ushort(a1);
}

// ---------------------------------------------------------------------------
// K0 (merged): blockIdx.x < 2048 -> X split (8 floats/thread);
// else -> W transpose+split (32x32 tiles). z = blockIdx.y selects q/k/v.
// ---------------------------------------------------------------------------
__global__ __launch_bounds__(256) void k_split(
    const float* __restrict__ X0, const float* __restrict__ X1, const float* __restrict__ X2,
    const float* __restrict__ W0, const float* __restrict__ W1, const float* __restrict__ W2)
{
    __shared__ float t[32][33];
    int z = blockIdx.y;
    int tid = threadIdx.x;
    if (blockIdx.x < 2048) {
        const float* X = (z == 0) ? X0 : (z == 1) ? X1 : X2;
        size_t i = (size_t)blockIdx.x * 256 + tid;          // group-of-8 index
        float4 v0 = ((const float4*)X)[2 * i];
        float4 v1 = ((const float4*)X)[2 * i + 1];
        float xs[8] = {v0.x, v0.y, v0.z, v0.w, v1.x, v1.y, v1.z, v1.w};
        uint16_t h[8], l[8];
        #pragma unroll
        for (int j = 0; j < 8; j++) split_h(xs[j], h[j], l[j]);
        uint4 hp, lp;
        hp.x = h[0] | ((uint32_t)h[1] << 16); hp.y = h[2] | ((uint32_t)h[3] << 16);
        hp.z = h[4] | ((uint32_t)h[5] << 16); hp.w = h[6] | ((uint32_t)h[7] << 16);
        lp.x = l[0] | ((uint32_t)l[1] << 16); lp.y = l[2] | ((uint32_t)l[3] << 16);
        lp.z = l[4] | ((uint32_t)l[5] << 16); lp.w = l[6] | ((uint32_t)l[7] << 16);
        size_t base = (size_t)z * MM * DM / 8;
        ((uint4*)g_Ah)[base + i] = hp;
        ((uint4*)g_Al)[base + i] = lp;
    } else {
        const float* W = (z == 0) ? W0 : (z == 1) ? W1 : W2;
        int id = blockIdx.x - 2048;          // 0..255
        int bx = (id & 15) * 32;             // n tile
        int by = (id >> 4) * 32;             // k tile
        int tx = tid & 31, ty = tid >> 5;    // (32, 8)
        #pragma unroll
        for (int r = ty; r < 32; r += 8)
            t[r][tx] = W[(size_t)(by + r) * DM + bx + tx];
        __syncthreads();
        size_t zoff = (size_t)z * DM * DM;
        #pragma unroll
        for (int r = ty; r < 32; r += 8) {
            float x = t[tx][r];              // = W[by+tx][bx+r]
            uint16_t h, l;
            split_h(x, h, l);
            g_Wh[zoff + (size_t)(bx + r) * DM + by + tx] = h;
            g_Wl[zoff + (size_t)(bx + r) * DM + by + tx] = l;
        }
    }
}

// ---------------------------------------------------------------------------
// K1: projection GEMM, 3xFP16 mma.sync (a0b0 + a1b0 + a0b1), cp.async double
// buffer + ldmatrix. CTA tile 128x128, BK=32, 8 warps 2(m)x4(n), warp 64x32.
// For z==2 (V): the staged output tile is exactly one 128-row segment x 128
// out-columns, so the epilogue ALSO emits the segment column totals to g_seg
// (light: ~70 LDS/thread + 1 sync in 1/3 of CTAs) — replaces k_segtot.
// ---------------------------------------------------------------------------
#define RSTH 40                        // row stride in halfs
#define TILE_H (128 * RSTH)            // 5120 halfs per tile
#define STAGE_H (4 * TILE_H)           // 20480 halfs per stage
#define PROJ_SMEM_BYTES (2 * STAGE_H * 2)   // 81920 B (=20480 floats)

__device__ __forceinline__ void ld_stage(uint32_t smb,
    const uint16_t* __restrict__ Ah, const uint16_t* __restrict__ Al,
    const uint16_t* __restrict__ Bh, const uint16_t* __restrict__ Bl,
    int k0, int tid)
{
    #pragma unroll
    for (int t = 0; t < 2; t++) {
        int idx = tid + t * 256;             // 0..511
        int row = idx >> 2;                  // 0..127
        int ch  = (idx & 3) * 8;             // half offset 0,8,16,24
        uint32_t d = smb + (uint32_t)(row * RSTH + ch) * 2;
        size_t s = (size_t)row * DM + k0 + ch;
        CP_ASYNC16(d,                    Ah + s);
        CP_ASYNC16(d + TILE_H * 2,       Al + s);
        CP_ASYNC16(d + 2 * TILE_H * 2,   Bh + s);
        CP_ASYNC16(d + 3 * TILE_H * 2,   Bl + s);
    }
}

__global__ __launch_bounds__(256, 2) void k_proj_mma2(
    const float* __restrict__ bq, const float* __restrict__ bk, const float* __restrict__ bv)
{
    extern __shared__ uint16_t smem_h[];
    const int z = blockIdx.z;
    const float* bias = (z == 0) ? bq : (z == 1) ? bk : bv;
    float* dst = (z == 0) ? g_Q : (z == 1) ? g_K : g_V;

    const int tid  = threadIdx.x;
    const int wid  = tid >> 5;
    const int lane = tid & 31;
    const int warp_m = wid >> 2;             // 0..1
    const int warp_n = wid & 3;              // 0..3
    const int m0 = blockIdx.y * 128;
    const int n0 = blockIdx.x * 128;

    const uint16_t* Ah = g_Ah + (size_t)z * MM * DM + (size_t)m0 * DM;
    const uint16_t* Al = g_Al + (size_t)z * MM * DM + (size_t)m0 * DM;
    const uint16_t* Bh = g_Wh + (size_t)z * DM * DM + (size_t)n0 * DM;
    const uint16_t* Bl = g_Wl + (size_t)z * DM * DM + (size_t)n0 * DM;

    const uint32_t smb = smem_addr_u32(smem_h);

    float c[4][4][4];
    #pragma unroll
    for (int mt = 0; mt < 4; mt++)
        #pragma unroll
        for (int nt = 0; nt < 4; nt++)
            #pragma unroll
            for (int i = 0; i < 4; i++) c[mt][nt][i] = 0.f;

    const int l7 = lane & 7;
    const int aRow  = warp_m * 64 + l7 + ((lane >> 3) & 1) * 8;
    const int aColH = ((lane >> 4) & 1) * 8;
    const int bRow  = warp_n * 32 + l7 + ((lane >> 4) & 1) * 8;
    const int bColH = ((lane >> 3) & 1) * 8;

    ld_stage(smb, Ah, Al, Bh, Bl, 0, tid);
    CP_COMMIT();

    const int NCHUNK = DM / 32;              // 16
    for (int ck = 0; ck < NCHUNK; ck++) {
        if (ck + 1 < NCHUNK) {
            ld_stage(smb + ((ck + 1) & 1) * STAGE_H * 2, Ah, Al, Bh, Bl, (ck + 1) * 32, tid);
            CP_COMMIT();
            CP_WAIT(1);
        } else {
            CP_WAIT(0);
        }
        __syncthreads();

        const uint32_t stage = smb + (ck & 1) * STAGE_H * 2;
        #pragma unroll
        for (int prod = 0; prod < 3; prod++) {
            const uint32_t aoff = stage + (prod == 1 ? TILE_H * 2 : 0);
            const uint32_t boff = stage + 2 * TILE_H * 2 + (prod == 2 ? TILE_H * 2 : 0);
            #pragma unroll
            for (int ks = 0; ks < 2; ks++) {
                const int kb = ks * 16;
                uint32_t af[4][4];
                #pragma unroll
                for (int mt = 0; mt < 4; mt++) {
                    uint32_t addr = aoff + (uint32_t)(((aRow + mt * 16) * RSTH) + kb + aColH) * 2;
                    LDSM_X4(af[mt][0], af[mt][1], af[mt][2], af[mt][3], addr);
                }
                uint32_t bf[4][2];
                #pragma unroll
                for (int pr = 0; pr < 2; pr++) {
                    uint32_t addr = boff + (uint32_t)(((bRow + pr * 16) * RSTH) + kb + bColH) * 2;
                    LDSM_X4(bf[pr * 2][0], bf[pr * 2][1], bf[pr * 2 + 1][0], bf[pr * 2 + 1][1], addr);
                }
                #pragma unroll
                for (int mt = 0; mt < 4; mt++)
                    #pragma unroll
                    for (int nt = 0; nt < 4; nt++)
                        mma_f16(c[mt][nt], af[mt][0], af[mt][1], af[mt][2], af[mt][3],
                                bf[nt][0], bf[nt][1]);
            }
        }
        __syncthreads();
    }

    // ---- epilogue: accum -> smem staging (stride 132 floats) -> coalesced ----
    float* stg = (float*)smem_h;             // 128 x 132 floats = 16896 floats
    float* sp  = stg + 128 * 132;            // 256 floats (half-column sums)
    const int fr = lane >> 2, fk = lane & 3;
    #pragma unroll
    for (int mt = 0; mt < 4; mt++) {
        #pragma unroll
        for (int nt = 0; nt < 4; nt++) {
            int m = warp_m * 64 + mt * 16 + fr;
            int n = warp_n * 32 + nt * 8 + fk * 2;
            stg[m * 132 + n]           = c[mt][nt][0];
            stg[m * 132 + n + 1]       = c[mt][nt][1];
            stg[(m + 8) * 132 + n]     = c[mt][nt][2];
            stg[(m + 8) * 132 + n + 1] = c[mt][nt][3];
        }
    }
    __syncthreads();
    for (int i = tid; i < 128 * 128; i += 256) {
        int row = i >> 7, col = i & 127;
        int n = n0 + col;
        int h = n >> 6, dd = n & 63;
        int mi = m0 + row;
        int b_ = mi >> 12, l = mi & (LL - 1);
        dst[(((size_t)(b_ * NH + h) * LL) + l) * HD + dd] = stg[row * 132 + col] + bias[n];
    }

    if (z == 2) {
        // ---- segment column totals (replaces k_segtot) ----
        int col = tid & 127, half = tid >> 7;
        float s = 0.f;
        #pragma unroll 8
        for (int r = 0; r < 64; r++) s += stg[(half * 64 + r) * 132 + col];
        sp[half * 128 + col] = s;
        __syncthreads();
        if (tid < 128) {
            int n = n0 + tid;
            int h = n >> 6, dd = n & 63;
            int b_ = m0 >> 12, seg = (m0 & (LL - 1)) >> 7;
            g_seg[((size_t)(b_ * NH + h) * NSEG + seg) * HD + dd] =
                sp[tid] + sp[128 + tid] + 128.f * bias[n];
        }
    }
}

// ---------------------------------------------------------------------------
// K2 (fused): blockIdx.x < 128 -> mscore; else -> cumsum segment (smem-staged
// 4-way scan with global prefix from g_seg — the R15 version; R16's stage-free
// variant regressed: mscore is L1-wavefront-bound, extra occupancy is useless).
// ---------------------------------------------------------------------------
__global__ __launch_bounds__(256) void k_fused1(const int* __restrict__ idx,
                                                float* __restrict__ out) {
    __shared__ __align__(16) char sb[(SEGL * HD + 4 * HD) * 4];   // 33 KB
    __shared__ float gpart[4 * HD];
    __shared__ float goffs[HD];
    int tid = threadIdx.x;
    int bh = blockIdx.y;
    if (blockIdx.x < LL / 32) {
        // ---------------- mscore ----------------
        int* sidx = (int*)sb;                 // 32*SK ints
        int l0 = blockIdx.x * 32;
        for (int i = tid; i < 32 * SK; i += 256) sidx[i] = idx[l0 * SK + i];
        __syncthreads();
        int wid = tid >> 5, lane = tid & 31;
        int grp = lane >> 3, sub = lane & 7;
        int lrel = wid * 4 + grp;
        int l = l0 + lrel;
        const float* Qb = g_Q + (size_t)bh * LL * HD;
        const float* Kb = g_K + (size_t)bh * LL * HD;
        float4 q0 = *(const float4*)&Qb[(size_t)l * HD + sub * 8];
        float4 q1 = *(const float4*)&Qb[(size_t)l * HD + sub * 8 + 4];
        const int* myidx = &sidx[lrel * SK];
        float mx = -INFINITY, sm = 0.f;
        #pragma unroll 6
        for (int s = 0; s < SK; s++) {
            int j = myidx[s];
            const float* kr = &Kb[(size_t)j * HD + sub * 8];
            float4 k0 = *(const float4*)kr;
            float4 k1 = *(const float4*)(kr + 4);
            float p = q0.x*k0.x + q0.y*k0.y + q0.z*k0.z + q0.w*k0.w
                    + q1.x*k1.x + q1.y*k1.y + q1.z*k1.z + q1.w*k1.w;
            p += __shfl_xor_sync(0xffffffffu, p, 4);
            p += __shfl_xor_sync(0xffffffffu, p, 2);
            p += __shfl_xor_sync(0xffffffffu, p, 1);
            mx = fmaxf(mx, p);
            sm += p;
        }
        if (sub == 0) g_m[bh * LL + l] = mx - sm * (1.f / LL);
    } else {
        // -------- cumsum segment: local 4-way scan + global prefix ----------
        int seg = blockIdx.x - LL / 32;       // 0..31
        float* tile = (float*)sb;             // SEGL*HD
        float* qtot = tile + SEGL * HD;       // 4*HD
        const float* Vb = g_V + (size_t)bh * LL * HD + (size_t)seg * SEGL * HD;
        int d = tid & 63, q = tid >> 6;
        {
            float s = 0.f;
            int lo = q * 8, hi = min(seg, lo + 8);
            for (int ss = lo; ss < hi; ss++)
                s += g_seg[((size_t)bh * NSEG + ss) * HD + d];
            gpart[q * HD + d] = s;
        }
        for (int i = tid; i < SEGL * HD; i += 256) tile[i] = Vb[i];
        __syncthreads();
        if (tid < HD)
            goffs[tid] = gpart[tid] + gpart[HD + tid] + gpart[2 * HD + tid] + gpart[3 * HD + tid];
        float acc = 0.f;
        #pragma unroll 8
        for (int r = 0; r < 32; r++) {
            int o = (q * 32 + r) * HD + d;
            acc += tile[o];
            tile[o] = acc;
        }
        qtot[q * HD + d] = acc;
        __syncthreads();
        float pre = goffs[d];
        for (int qq = 0; qq < q; qq++) pre += qtot[qq * HD + d];
        #pragma unroll 8
        for (int r = 0; r < 32; r++) tile[(q * 32 + r) * HD + d] += pre;
        __syncthreads();
        int b_ = bh >> 3, h = bh & 7;
        for (int i = tid; i < SEGL * HD; i += 256) {
            int l = seg * SEGL + (i >> 6), dd = i & 63;
            out[((size_t)b_ * LL + l) * DM + h * HD + dd] = tile[i];
        }
    }
}

// ---------------------------------------------------------------------------
// K3: radix top-45 per (b,h) (also zeroes g_rowsum). Grid = BH.
// ---------------------------------------------------------------------------
__global__ __launch_bounds__(256) void k_topk() {
    __shared__ uint32_t keys[LL];            // 16 KB
    __shared__ uint32_t hist[256];
    __shared__ uint32_t s_prefix, s_need;
    __shared__ int s_cnt, s_eq;
    __shared__ int eq_list[256];
    int bh = blockIdx.x, tid = threadIdx.x;
    if (tid < SK) g_rowsum[bh * SK + tid] = 0.f;
    for (int i = tid; i < LL; i += 256) {
        uint32_t u = __float_as_uint(g_m[bh * LL + i]);
        keys[i] = (u & 0x80000000u) ? ~u : (u | 0x80000000u);
    }
    if (tid == 0) { s_prefix = 0; s_need = SK; s_cnt = 0; s_eq = 0; }
    __syncthreads();
    for (int level = 0; level < 4; level++) {
        int shift = 24 - 8 * level;
        uint32_t pmask = (level == 0) ? 0u : (0xFFFFFFFFu << (shift + 8));
        hist[tid] = 0;
        __syncthreads();
        uint32_t prefix = s_prefix;
        for (int i = tid; i < LL; i += 256) {
            uint32_t u = keys[i];
            if ((u & pmask) == prefix) atomicAdd(&hist[(u >> shift) & 0xFFu], 1u);
        }
        __syncthreads();
        if (tid == 0) {
            uint32_t need = s_need, S = 0; int b;
            for (b = 255; b > 0; b--) {
                if (S + hist[b] >= need) break;
                S += hist[b];
            }
            s_prefix = prefix | ((uint32_t)b << shift);
            s_need = need - S;
        }
        __syncthreads();
    }
    uint32_t thresh = s_prefix;
    uint32_t need_eq = s_need;
    for (int i = tid; i < LL; i += 256) {
        uint32_t u = keys[i];
        if (u > thresh) {
            int p = atomicAdd(&s_cnt, 1);
            g_top[bh * SK + p] = i;
        } else if (u == thresh) {
            int p = atomicAdd(&s_eq, 1);
            if (p < 256) eq_list[p] = i;
        }
    }
    __syncthreads();
    if (tid == 0) {
        int E = s_eq < 256 ? s_eq : 256;
        int base = s_cnt;
        for (uint32_t t = 0; t < need_eq; t++) {
            int best = 1 << 30, bj = 0;
            for (int j2 = 0; j2 < E; j2++)
                if (eq_list[j2] < best) { best = eq_list[j2]; bj = j2; }
            g_top[bh * SK + base + t] = best;
            eq_list[bj] = 1 << 30;
        }
    }
}

// ---------------------------------------------------------------------------
// K4: fused scores+updpart. Block = (jseg of 128 keys, bh); JSEGS=32 for
// load balance under the causal skip. V staged TRANSPOSED (vs[d][jj],
// stride 68) so the accumulate is float4 x float4 (conflict-free LDS.128).
// ---------------------------------------------------------------------------
#define SU_QS 0
#define SU_KS (SK*HD)                 // 2880
#define SU_VS (SU_KS + 64*68)         // 7232
#define SU_ES (SU_VS + 64*68)         // 11584
#define SU_FLOATS (SU_ES + SK*64)     // 14464
#define SU_BYTES (SU_FLOATS * 4)      // 57856

__global__ __launch_bounds__(256) void k_scoreupd() {
    extern __shared__ float sm[];
    __shared__ int   tp[SK];
    __shared__ float rs[SK];
    int jseg = blockIdx.x, bh = blockIdx.y, tid = threadIdx.x;
    const float* Qb = g_Q + (size_t)bh * LL * HD;
    const float* Kb = g_K + (size_t)bh * LL * HD;
    const float* Vb = g_V + (size_t)bh * LL * HD;
    if (tid < SK) { tp[tid] = g_top[bh * SK + tid]; rs[tid] = 0.f; }
    __syncthreads();
    float* qs = sm + SU_QS;
    float* ks = sm + SU_KS;
    float* vs = sm + SU_VS;   // transposed: vs[d*68 + jj]
    float* es = sm + SU_ES;
    for (int i = tid; i < SK * HD; i += 256)
        qs[i] = Qb[(size_t)tp[i >> 6] * HD + (i & 63)];
    int key = tid & 63, ug = tid >> 6;
    float acc[12];
    #pragma unroll
    for (int c = 0; c < 12; c++) acc[c] = 0.f;

    for (int sc = 0; sc < 2; sc++) {
        int jc = jseg * 128 + sc * 64;
        __syncthreads();                      // protect ks/vs/es reuse
        for (int i = tid; i < 64 * HD; i += 256) {
            int jj = i >> 6, dd = i & 63;
            ks[jj * 68 + dd] = Kb[(size_t)(jc + jj) * HD + dd];
            vs[dd * 68 + jj] = Vb[(size_t)(jc + jj) * HD + dd];
        }
        __syncthreads();
        const float4* ka = (const float4*)&ks[key * 68];
        for (int u = ug; u < SK; u += 4) {
            int t = tp[u];
            if (t >= jc) {                    // warp-uniform
                const float4* qa = (const float4*)&qs[u * HD];
                float a = 0.f;
                #pragma unroll
                for (int dq = 0; dq < 16; dq++) {
                    float4 qq = qa[dq], kk = ka[dq];
                    a += qq.x * kk.x + qq.y * kk.y + qq.z * kk.z + qq.w * kk.w;
                }
                float e = (jc + key > t) ? 0.f : __expf(a * 0.125f);
                es[u * 64 + key] = e;
                float r = e;
                #pragma unroll
                for (int o = 16; o; o >>= 1) r += __shfl_xor_sync(0xffffffffu, r, o);
                if ((tid & 31) == 0) atomicAdd(&rs[u], r);
            } else {
                es[u * 64 + key] = 0.f;
            }
        }
        __syncthreads();
        // accumulate e . V with transposed vs: float4 x float4
        const float4* va = (const float4*)&vs[key * 68];
        int c = 0;
        for (int u = ug; u < SK; u += 4, c++) {
            if (tp[u] >= jc) {                // warp-uniform
                const float4* ea = (const float4*)&es[u * 64];
                float a = acc[c];
                #pragma unroll
                for (int j4 = 0; j4 < 16; j4++) {
                    float4 ee = ea[j4], vv = va[j4];
                    a += ee.x * vv.x + ee.y * vv.y + ee.z * vv.z + ee.w * vv.w;
                }
                acc[c] = a;
            }
        }
    }
    __syncthreads();
    int c = 0;
    for (int u = ug; u < SK; u += 4, c++)
        g_part[(((size_t)bh * JSEGS + jseg) * SK + u) * HD + key] = acc[c];
    if (tid < SK && rs[tid] != 0.f) atomicAdd(&g_rowsum[bh * SK + tid], rs[tid]);
}

// K5: reduce partials, normalize by row sum, scatter into out at top rows.
__global__ void k_scatter(float* __restrict__ out) {
    int u = blockIdx.x, bh = blockIdx.y, d = threadIdx.x;
    float s = 0.f;
    #pragma unroll
    for (int seg = 0; seg < JSEGS; seg++)
        s += g_part[(((size_t)bh * JSEGS + seg) * SK + u) * HD + d];
    s *= (1.f / g_rowsum[bh * SK + u]);
    int b_ = bh >> 3, h = bh & 7, l = g_top[bh * SK + u];
    out[((size_t)b_ * LL + l) * DM + h * HD + d] = s;
}

// ---------------------------------------------------------------------------
extern "C" void kernel_launch(void* const* d_in, const int* in_sizes, int n_in,
                              void* d_out, int out_size) {
    const float* queries = (const float*)d_in[0];
    const float* keys    = (const float*)d_in[1];
    const float* values  = (const float*)d_in[2];
    const float* Wq = (const float*)d_in[3];
    const float* bq = (const float*)d_in[4];
    const float* Wk = (const float*)d_in[5];
    const float* bk = (const float*)d_in[6];
    const float* Wv = (const float*)d_in[7];
    const float* bv = (const float*)d_in[8];
    const int*   idx = (const int*)d_in[9];
    float* out = (float*)d_out;

    cudaFuncSetAttribute(k_proj_mma2, cudaFuncAttributeMaxDynamicSharedMemorySize,
                         PROJ_SMEM_BYTES);
    cudaFuncSetAttribute(k_scoreupd, cudaFuncAttributeMaxDynamicSharedMemorySize,
                         SU_BYTES);

    k_split<<<dim3(2048 + 256, 3), 256>>>(queries, keys, values, Wq, Wk, Wv);
    k_proj_mma2<<<dim3(DM / 128, MM / 128, 3), 256, PROJ_SMEM_BYTES>>>(bq, bk, bv);
    k_fused1<<<dim3(LL / 32 + NSEG, BH), 256>>>(idx, out);
    k_topk<<<BH, 256>>>();
    k_scoreupd<<<dim3(JSEGS, BH), 256, SU_BYTES>>>();
    k_scatter<<<dim3(SK, BH), 64>>>(out);
}